// round 1
// baseline (speedup 1.0000x reference)
#include <cuda_runtime.h>
#include <stdint.h>
#include <math.h>

// Problem constants (fixed shapes from reference: scores (128, 4096, 2))
#define NN   4096
#define BSZ  128
#define ENS  2
#define BE   256           // BSZ*ENS
#define KK   32
#define NEGC (-1e30f)
#define HALF_OUT 1048576   // 128*4096*2

// ---------------- scratch (static device memory; no allocations) ----------------
__device__ float    g_B[(size_t)(NN + 1) * BE * KK]; // B[i][b][j-1], j=1..32 (col 0 is identically 0)
__device__ float    g_U[(size_t)BE * NN];            // uniforms, layout [b*NN + i]
__device__ unsigned g_mask[(size_t)NN * BE];         // per-(i,b) 32-bit inclusion-threshold mask, bit l <-> r=l+1
__device__ float    g_S[(size_t)NN * BE];            // th + log_ekm1, layout [i*BE + b]
__device__ float    g_logZ[BE];
__device__ unsigned g_bits[(size_t)BE * (NN / 32)];  // sampled bits, [b*128 + i/32], bit (i&31)

// ---------------- threefry2x32, key = (0, 42) (jax.random.key(42)) ----------------
// Partitionable mode (JAX default since ~0.4.36): counter is 64-bit iota ->
// (hi=0, lo=i); 32-bit output = out0 ^ out1.
__device__ __forceinline__ uint32_t tf_bits(uint32_t lo)
{
    uint32_t x0 = 0u;        // hi word of 64-bit counter (size < 2^32 -> 0)
    uint32_t x1 = lo;
    const uint32_t ks0 = 0u, ks1 = 42u, ks2 = 0x1BD11BF0u; // 0 ^ 42 ^ 0x1BD11BDA
    x0 += ks0; x1 += ks1;
#define TFR(r) { x0 += x1; x1 = (x1 << (r)) | (x1 >> (32 - (r))); x1 ^= x0; }
    TFR(13) TFR(15) TFR(26) TFR(6)   x0 += ks1; x1 += ks2 + 1u;
    TFR(17) TFR(29) TFR(16) TFR(24)  x0 += ks2; x1 += ks0 + 2u;
    TFR(13) TFR(15) TFR(26) TFR(6)   x0 += ks0; x1 += ks1 + 3u;
    TFR(17) TFR(29) TFR(16) TFR(24)  x0 += ks1; x1 += ks2 + 4u;
    TFR(13) TFR(15) TFR(26) TFR(6)   x0 += ks2; x1 += ks0 + 5u;
#undef TFR
    return x0 ^ x1;
}

// K0: uniforms, exactly jax.random.uniform bit path:
// u = bitcast((bits>>9)|0x3f800000) - 1; u = max(u, 0)
__global__ void k_rand()
{
    int tid = blockIdx.x * blockDim.x + threadIdx.x;   // 0 .. 2^20-1
    int b = tid >> 12;
    int i = tid & (NN - 1);
    uint32_t idx = (uint32_t)(i * BE + b);             // flat index into (N, T, BE)
    uint32_t bits = tf_bits(idx);
    float f = __uint_as_float((bits >> 9) | 0x3f800000u) - 1.0f;
    g_U[(size_t)b * NN + i] = fmaxf(f, 0.0f);
}

// jnp.logaddexp fp32 mirror: max(x,y) + log1p(exp(-|x-y|)), delta = x - y
__device__ __forceinline__ float logaddexpf32(float x, float y)
{
    float d = x - y;
    return fmaxf(x, y) + log1pf(expf(-fabsf(d)));
}

// K1: backward scan. One warp per batch entry b. Lane l holds B-state for j=l+1.
// Produces g_B rows for i=0..NN (row NN = init) and the per-step inclusion masks.
__global__ void k_backward(const float* __restrict__ scores)
{
    int warp = (blockIdx.x * blockDim.x + threadIdx.x) >> 5;
    int lane = threadIdx.x & 31;
    if (warp >= BE) return;
    int b = warp;
    const int bz = b >> 1, e = b & 1;
    const float* thbase = scores + (size_t)bz * (NN * ENS) + e;  // flat(b,i) = thbase[2*i]

    float E = NEGC;
    g_B[((size_t)NN * BE + b) * KK + lane] = NEGC;               // init row (i = NN)

    for (int blk = NN / 32 - 1; blk >= 0; --blk) {
        int base = blk * 32;
        float thv = thbase[2 * (base + lane)];
        float uv  = g_U[(size_t)b * NN + base + lane];
#pragma unroll 8
        for (int ii = 31; ii >= 0; --ii) {
            int i = base + ii;
            float th = __shfl_sync(0xffffffffu, thv, ii);
            float u  = __shfl_sync(0xffffffffu, uv,  ii);
            float Ep = __shfl_up_sync(0xffffffffu, E, 1);
            if (lane == 0) Ep = 0.0f;                 // B[i+1][0] = log e_0 = 0
            float shifted = Ep + th;                  // th + B[i+1][r-1], r = lane+1
            float Enew = logaddexpf32(E, shifted);    // B[i][r]
            float logq = shifted - Enew;              // (th + B[i+1][r-1]) - B[i][r]
            float q = expf(fminf(logq, 0.0f));
            unsigned m = __ballot_sync(0xffffffffu, u < q);
            E = Enew;
            g_B[((size_t)i * BE + b) * KK + lane] = E;
            if (lane == 0) g_mask[(size_t)i * BE + b] = m;
        }
    }
}

// K2: forward scan. Lane l holds F-state for j=l+1. Computes per-step
// s_i = th_i + logsumexp_j(F[i][j] + B[i+1][31-j]) and finally logZ = F[N][32].
__global__ void k_forward(const float* __restrict__ scores)
{
    int warp = (blockIdx.x * blockDim.x + threadIdx.x) >> 5;
    int lane = threadIdx.x & 31;
    if (warp >= BE) return;
    int b = warp;
    const int bz = b >> 1, e = b & 1;
    const float* thbase = scores + (size_t)bz * (NN * ENS) + e;

    float F = NEGC;
    for (int blk = 0; blk < NN / 32; ++blk) {
        int base = blk * 32;
        float thv = thbase[2 * (base + lane)];
#pragma unroll 4
        for (int ii = 0; ii < 32; ++ii) {
            int i = base + ii;
            float th = __shfl_sync(0xffffffffu, thv, ii);
            // B[i+1] columns: col l (l>=1) stored at offset l-1; col 0 == 0
            float Bv = 0.0f;
            if (lane >= 1) Bv = g_B[((size_t)(i + 1) * BE + b) * KK + (lane - 1)];
            // F[i][l] on lane l: lane l-1's state (lane 0 -> F[i][0] = 0)
            float Fl = __shfl_up_sync(0xffffffffu, F, 1);
            if (lane == 0) Fl = 0.0f;
            float Bt = __shfl_sync(0xffffffffu, Bv, 31 - lane);   // B[i+1][31-l]
            float comb = Fl + Bt;
            // warp logsumexp over 32 lanes
            float cmax = comb;
#pragma unroll
            for (int s = 16; s; s >>= 1) cmax = fmaxf(cmax, __shfl_xor_sync(0xffffffffu, cmax, s));
            float ex = expf(comb - cmax);
            float ssum = ex;
#pragma unroll
            for (int s = 16; s; s >>= 1) ssum += __shfl_xor_sync(0xffffffffu, ssum, s);
            float L = logf(ssum) + cmax;
            if (lane == 0) g_S[(size_t)i * BE + b] = th + L;
            // scan update (uses pre-update state via Fl)
            float shifted = Fl + th;
            F = logaddexpf32(F, shifted);
        }
    }
    if (lane == 31) g_logZ[b] = F;   // F[N][32] = logZ
}

// K3: sequential conditional-Poisson bit scan per batch entry (pure bit extract).
__global__ void k_sample()
{
    int b = blockIdx.x * blockDim.x + threadIdx.x;   // 256 threads total
    if (b >= BE) return;
    int r = KK;
    unsigned w = 0u;
    for (int blk = 0; blk < NN / 32; ++blk) {
#pragma unroll
        for (int ii = 0; ii < 32; ++ii) {
            int i = blk * 32 + ii;
            unsigned m = g_mask[(size_t)i * BE + b];
            unsigned incl = (unsigned)(r > 0) & ((m >> ((unsigned)(r - 1) & 31u)) & 1u);
            r -= (int)incl;
            w |= incl << ii;
        }
        g_bits[(size_t)b * (NN / 32) + blk] = w;
        w = 0u;
    }
}

// K4: finalize outputs.
// out[0 .. 2^20)        = new_mask (1,128,4096,2): (s - m) + m  (straight-through value)
// out[2^20 .. 2*2^20)   = new_marginals (128,4096,2): m = exp(s_i - logZ_b)
__global__ void k_final(float* __restrict__ out)
{
    int tid = blockIdx.x * blockDim.x + threadIdx.x;  // 0 .. 2^20-1
    int bz = tid >> 13;
    int rem = tid & 8191;
    int n = rem >> 1;
    int e = rem & 1;
    int be = bz * ENS + e;
    float s = (float)((g_bits[(size_t)be * (NN / 32) + (n >> 5)] >> (n & 31)) & 1u);
    float m = expf(g_S[(size_t)n * BE + be] - g_logZ[be]);
    out[tid] = (s - m) + m;
    out[HALF_OUT + tid] = m;
}

extern "C" void kernel_launch(void* const* d_in, const int* in_sizes, int n_in,
                              void* d_out, int out_size)
{
    const float* scores = (const float*)d_in[0];
    float* out = (float*)d_out;
    (void)in_sizes; (void)n_in; (void)out_size;

    k_rand<<<1024, 1024>>>();
    k_backward<<<64, 128>>>(scores);
    k_forward<<<64, 128>>>(scores);
    k_sample<<<8, 32>>>();
    k_final<<<1024, 1024>>>(out);
}

// round 2
// speedup vs baseline: 3.0215x; 3.0215x over previous
#include <cuda_runtime.h>
#include <stdint.h>
#include <math.h>

// Problem constants (fixed shapes from reference: scores (128, 4096, 2))
#define NN   4096
#define BSZ  128
#define ENS  2
#define BE   256           // BSZ*ENS
#define KK   32
#define NEGC (-1e30f)
#define HALF_OUT 1048576   // 128*4096*2

// ---------------- scratch (static device memory; no allocations) ----------------
__device__ float    g_B[(size_t)(NN + 1) * BE * KK]; // B[i][b][j-1], j=1..32 (col 0 is identically 0)
__device__ float    g_F[(size_t)NN * BE * KK];       // F[i][b][j], j=0..31 (pre-update state at step i)
__device__ float    g_U[(size_t)BE * NN];            // uniforms, layout [b*NN + i]
__device__ unsigned g_mask[(size_t)BE * NN];         // per-(b,i) 32-bit inclusion-threshold mask, bit l <-> r=l+1
__device__ float    g_S[(size_t)NN * BE];            // th + log_ekm1, layout [i*BE + b]
__device__ float    g_T[(size_t)NN * BE];            // transposed theta, [i*BE + b]
__device__ float    g_logZ[BE];
__device__ unsigned g_bits[(size_t)BE * (NN / 32)];  // sampled bits, [b*128 + i/32], bit (i&31)

// ---------------- threefry2x32, key = (0, 42) (jax.random.key(42)) ----------------
__device__ __forceinline__ uint32_t tf_bits(uint32_t lo)
{
    uint32_t x0 = 0u;
    uint32_t x1 = lo;
    const uint32_t ks0 = 0u, ks1 = 42u, ks2 = 0x1BD11BF0u; // 0 ^ 42 ^ 0x1BD11BDA
    x0 += ks0; x1 += ks1;
#define TFR(r) { x0 += x1; x1 = (x1 << (r)) | (x1 >> (32 - (r))); x1 ^= x0; }
    TFR(13) TFR(15) TFR(26) TFR(6)   x0 += ks1; x1 += ks2 + 1u;
    TFR(17) TFR(29) TFR(16) TFR(24)  x0 += ks2; x1 += ks0 + 2u;
    TFR(13) TFR(15) TFR(26) TFR(6)   x0 += ks0; x1 += ks1 + 3u;
    TFR(17) TFR(29) TFR(16) TFR(24)  x0 += ks1; x1 += ks2 + 4u;
    TFR(13) TFR(15) TFR(26) TFR(6)   x0 += ks2; x1 += ks0 + 5u;
#undef TFR
    return x0 ^ x1;
}

// K0: uniforms, exactly jax.random.uniform bit path
__global__ void k_rand()
{
    int tid = blockIdx.x * blockDim.x + threadIdx.x;   // 0 .. 2^20-1
    int b = tid >> 12;
    int i = tid & (NN - 1);
    uint32_t idx = (uint32_t)(i * BE + b);
    uint32_t bits = tf_bits(idx);
    float f = __uint_as_float((bits >> 9) | 0x3f800000u) - 1.0f;
    g_U[(size_t)b * NN + i] = fmaxf(f, 0.0f);
}

// K0b: transpose theta into [i*BE + b] for coalesced access in k_comb
__global__ void k_tr(const float* __restrict__ scores)
{
    int tid = blockIdx.x * blockDim.x + threadIdx.x;   // 0 .. 2^20-1 = i*BE + b
    int b = tid & (BE - 1);
    int i = tid >> 8;
    int bz = b >> 1, e = b & 1;
    g_T[tid] = scores[(size_t)bz * (NN * ENS) + i * ENS + e];
}

// jnp.logaddexp fp32 mirror (EXACT path, used for sampling-critical backward scan)
__device__ __forceinline__ float logaddexpf32(float x, float y)
{
    float d = x - y;
    return fmaxf(x, y) + log1pf(expf(-fabsf(d)));
}

// K1: backward scan. One warp per batch entry b. Lane l holds B-state for j=l+1.
// NUMERICS UNCHANGED from the passing version — only the mask store layout changed.
__global__ void k_backward(const float* __restrict__ scores)
{
    int warp = (blockIdx.x * blockDim.x + threadIdx.x) >> 5;
    int lane = threadIdx.x & 31;
    if (warp >= BE) return;
    int b = warp;
    const int bz = b >> 1, e = b & 1;
    const float* thbase = scores + (size_t)bz * (NN * ENS) + e;

    float E = NEGC;
    g_B[((size_t)NN * BE + b) * KK + lane] = NEGC;               // init row (i = NN)

    for (int blk = NN / 32 - 1; blk >= 0; --blk) {
        int base = blk * 32;
        float thv = thbase[2 * (base + lane)];
        float uv  = g_U[(size_t)b * NN + base + lane];
#pragma unroll 8
        for (int ii = 31; ii >= 0; --ii) {
            int i = base + ii;
            float th = __shfl_sync(0xffffffffu, thv, ii);
            float u  = __shfl_sync(0xffffffffu, uv,  ii);
            float Ep = __shfl_up_sync(0xffffffffu, E, 1);
            if (lane == 0) Ep = 0.0f;
            float shifted = Ep + th;
            float Enew = logaddexpf32(E, shifted);
            float logq = shifted - Enew;
            float q = expf(fminf(logq, 0.0f));
            unsigned m = __ballot_sync(0xffffffffu, u < q);
            E = Enew;
            g_B[((size_t)i * BE + b) * KK + lane] = E;
            if (lane == 0) g_mask[(size_t)b * NN + i] = m;
        }
    }
}

// K2: forward scan (marginals path, 1e-3 tolerance). Pure register scan with fast
// intrinsics, no memory on the dependency chain. Lane j (0..31) holds F[i][j].
// Stores the PRE-update state for every i (F[i] pairs with B[i+1] in the comb).
__global__ void k_fscan(const float* __restrict__ scores)
{
    int warp = (blockIdx.x * blockDim.x + threadIdx.x) >> 5;
    int lane = threadIdx.x & 31;
    if (warp >= BE) return;
    int b = warp;
    const int bz = b >> 1, e = b & 1;
    const float* thbase = scores + (size_t)bz * (NN * ENS) + e;

    float F = (lane == 0) ? 0.0f : NEGC;   // log e_j of empty set
    for (int blk = 0; blk < NN / 32; ++blk) {
        int base = blk * 32;
        float thv = thbase[2 * (base + lane)];
#pragma unroll 8
        for (int ii = 0; ii < 32; ++ii) {
            int i = base + ii;
            g_F[((size_t)i * BE + b) * KK + lane] = F;   // pre-update state
            float th = __shfl_sync(0xffffffffu, thv, ii);
            float Fp = __shfl_up_sync(0xffffffffu, F, 1);
            if (lane == 0) Fp = NEGC;                    // F[j-1] for j=0 -> none
            float sh = Fp + th;
            float d  = F - sh;
            F = fmaxf(F, sh) + __logf(1.0f + __expf(-fabsf(d)));
        }
    }
}

// K3: comb + logsumexp. One thread per (i,b); streams F and B rows (coalesced
// 4KB per warp) with no serial chain — latency fully hidden by parallelism.
// s_i = th_i + log sum_j exp(F[i][j] + B[i+1][31-j])
__global__ void k_comb()
{
    int tid = blockIdx.x * blockDim.x + threadIdx.x;  // 0 .. 2^20-1 = i*BE + b
    int b = tid & (BE - 1);
    int i = tid >> 8;

    const float4* Fr = reinterpret_cast<const float4*>(&g_F[((size_t)i * BE + b) * KK]);
    const float4* Br = reinterpret_cast<const float4*>(&g_B[((size_t)(i + 1) * BE + b) * KK]);

    float Fv[32], Bv[32];
#pragma unroll
    for (int q = 0; q < 8; ++q) {
        float4 f4 = Fr[q];
        Fv[4 * q + 0] = f4.x; Fv[4 * q + 1] = f4.y; Fv[4 * q + 2] = f4.z; Fv[4 * q + 3] = f4.w;
        float4 b4 = Br[q];
        Bv[4 * q + 0] = b4.x; Bv[4 * q + 1] = b4.y; Bv[4 * q + 2] = b4.z; Bv[4 * q + 3] = b4.w;
    }

    float comb[32];
#pragma unroll
    for (int j = 0; j < 32; ++j) {
        float bc = (j == 31) ? 0.0f : Bv[30 - j];   // B[i+1][31-j]; col 0 == 0
        comb[j] = Fv[j] + bc;
    }
    float mx = comb[0];
#pragma unroll
    for (int j = 1; j < 32; ++j) mx = fmaxf(mx, comb[j]);
    float s = 0.0f;
#pragma unroll
    for (int j = 0; j < 32; ++j) s += __expf(comb[j] - mx);

    g_S[tid] = g_T[tid] + mx + __logf(s);
}

// K4: sequential conditional-Poisson bit scan, thread per b, double-buffered
// uint4 mask loads so L2 latency overlaps the pure-ALU bit chain.
__device__ __forceinline__ void samp_word(unsigned m, int ii, unsigned& r, unsigned& w)
{
    unsigned incl = (unsigned)(r > 0) & ((m >> ((r - 1u) & 31u)) & 1u);
    r -= incl;
    w |= incl << ii;
}

__device__ __forceinline__ unsigned samp_block(const uint4* buf, unsigned& r)
{
    unsigned w = 0;
#pragma unroll
    for (int q = 0; q < 8; ++q) {
        uint4 v = buf[q];
        samp_word(v.x, 4 * q + 0, r, w);
        samp_word(v.y, 4 * q + 1, r, w);
        samp_word(v.z, 4 * q + 2, r, w);
        samp_word(v.w, 4 * q + 3, r, w);
    }
    return w;
}

__global__ void k_sample()
{
    int b = blockIdx.x * blockDim.x + threadIdx.x;
    if (b >= BE) return;
    g_logZ[b] = g_B[(size_t)b * KK + 31];   // B[0][b][32] = log e_k(all) = logZ

    const uint4* mp = reinterpret_cast<const uint4*>(g_mask + (size_t)b * NN);
    unsigned r = KK;
    uint4 A[8], Bb[8];
#pragma unroll
    for (int q = 0; q < 8; ++q) A[q] = mp[q];

    for (int blk = 0; blk < 128; blk += 2) {
#pragma unroll
        for (int q = 0; q < 8; ++q) Bb[q] = mp[(blk + 1) * 8 + q];
        g_bits[(size_t)b * 128 + blk] = samp_block(A, r);
        if (blk + 2 < 128) {
#pragma unroll
            for (int q = 0; q < 8; ++q) A[q] = mp[(blk + 2) * 8 + q];
        }
        g_bits[(size_t)b * 128 + blk + 1] = samp_block(Bb, r);
    }
}

// K5: finalize outputs.
__global__ void k_final(float* __restrict__ out)
{
    int tid = blockIdx.x * blockDim.x + threadIdx.x;  // 0 .. 2^20-1
    int bz = tid >> 13;
    int rem = tid & 8191;
    int n = rem >> 1;
    int e = rem & 1;
    int be = bz * ENS + e;
    float s = (float)((g_bits[(size_t)be * (NN / 32) + (n >> 5)] >> (n & 31)) & 1u);
    float m = __expf(g_S[(size_t)n * BE + be] - g_logZ[be]);
    out[tid] = (s - m) + m;
    out[HALF_OUT + tid] = m;
}

extern "C" void kernel_launch(void* const* d_in, const int* in_sizes, int n_in,
                              void* d_out, int out_size)
{
    const float* scores = (const float*)d_in[0];
    float* out = (float*)d_out;
    (void)in_sizes; (void)n_in; (void)out_size;

    k_rand<<<1024, 1024>>>();
    k_tr<<<1024, 1024>>>(scores);
    k_backward<<<64, 128>>>(scores);
    k_fscan<<<64, 128>>>(scores);
    k_comb<<<4096, 256>>>();
    k_sample<<<8, 32>>>();
    k_final<<<1024, 1024>>>(out);
}

// round 3
// speedup vs baseline: 3.6482x; 1.2074x over previous
#include <cuda_runtime.h>
#include <stdint.h>
#include <math.h>

// Problem constants (fixed shapes from reference: scores (128, 4096, 2))
#define NN   4096
#define BSZ  128
#define ENS  2
#define BE   256           // BSZ*ENS
#define KK   32
#define NEGC (-1e30f)
#define HALF_OUT 1048576   // 128*4096*2
#define NCHUNK 32
#define CLEN   128         // NN / NCHUNK

// ---------------- scratch (static device memory; no allocations) ----------------
__device__ float    g_B[(size_t)(NN + 1) * BE * KK]; // B[i][b][j-1], j=1..32 (col 0 is identically 0)
__device__ float    g_U[(size_t)BE * NN];            // uniforms, layout [b*NN + i]
__device__ unsigned g_mask[(size_t)BE * NN];         // per-(b,i) inclusion mask, bit l <-> r=l+1
__device__ float    g_CE[(size_t)BE * NCHUNK * KK];  // chunk ESPs L_c[b][c][j], j=0..31
__device__ float    g_BD[(size_t)BE * NCHUNK * KK];  // chunk boundary prefix states P_c
__device__ float    g_M[(size_t)BE * NN];            // marginals, [b*NN + i]
__device__ float    g_logZ[BE];
__device__ unsigned g_bits[(size_t)BE * (NN / 32)];  // sampled bits, [b*128 + i/32]

// ---------------- threefry2x32, key = (0, 42) ----------------
__device__ __forceinline__ uint32_t tf_bits(uint32_t lo)
{
    uint32_t x0 = 0u;
    uint32_t x1 = lo;
    const uint32_t ks0 = 0u, ks1 = 42u, ks2 = 0x1BD11BF0u;
    x0 += ks0; x1 += ks1;
#define TFR(r) { x0 += x1; x1 = (x1 << (r)) | (x1 >> (32 - (r))); x1 ^= x0; }
    TFR(13) TFR(15) TFR(26) TFR(6)   x0 += ks1; x1 += ks2 + 1u;
    TFR(17) TFR(29) TFR(16) TFR(24)  x0 += ks2; x1 += ks0 + 2u;
    TFR(13) TFR(15) TFR(26) TFR(6)   x0 += ks0; x1 += ks1 + 3u;
    TFR(17) TFR(29) TFR(16) TFR(24)  x0 += ks1; x1 += ks2 + 4u;
    TFR(13) TFR(15) TFR(26) TFR(6)   x0 += ks2; x1 += ks0 + 5u;
#undef TFR
    return x0 ^ x1;
}

__global__ void k_rand()
{
    int tid = blockIdx.x * blockDim.x + threadIdx.x;
    int b = tid >> 12;
    int i = tid & (NN - 1);
    uint32_t bits = tf_bits((uint32_t)(i * BE + b));
    float f = __uint_as_float((bits >> 9) | 0x3f800000u) - 1.0f;
    g_U[(size_t)b * NN + i] = fmaxf(f, 0.0f);
}

// EXACT logaddexp (libdevice expf/log1pf — bitwise path for sampling masks)
__device__ __forceinline__ float logaddexpf32(float x, float y)
{
    float d = x - y;
    return fmaxf(x, y) + log1pf(expf(-fabsf(d)));
}

// Fast logaddexp (marginals path, 1e-3 tolerance)
__device__ __forceinline__ float logaddexp_fast(float x, float y)
{
    float d = x - y;
    return fmaxf(x, y) + __logf(1.0f + __expf(-fabsf(d)));
}

// L1: fused kernel. Blocks [0,64): exact backward scan (numerics UNCHANGED —
// bit-identical to the passing version). Blocks [64, 2112): fscan phase A
// (per-chunk local ESPs of 128 elements, fast math).
__global__ void k_scanAB(const float* __restrict__ scores)
{
    int lane = threadIdx.x & 31;

    if (blockIdx.x < 64) {
        // ------- backward scan, warp per b -------
        int b = blockIdx.x * 4 + (threadIdx.x >> 5);
        const int bz = b >> 1, e = b & 1;
        const float* thbase = scores + (size_t)bz * (NN * ENS) + e;

        float E = NEGC;
        g_B[((size_t)NN * BE + b) * KK + lane] = NEGC;   // init row (i = NN)

        for (int blk = NN / 32 - 1; blk >= 0; --blk) {
            int base = blk * 32;
            float thv = thbase[2 * (base + lane)];
            float uv  = g_U[(size_t)b * NN + base + lane];
#pragma unroll 8
            for (int ii = 31; ii >= 0; --ii) {
                int i = base + ii;
                float th = __shfl_sync(0xffffffffu, thv, ii);
                float u  = __shfl_sync(0xffffffffu, uv,  ii);
                float Ep = __shfl_up_sync(0xffffffffu, E, 1);
                if (lane == 0) Ep = 0.0f;
                float shifted = Ep + th;
                float Enew = logaddexpf32(E, shifted);
                float logq = shifted - Enew;
                float q = expf(fminf(logq, 0.0f));
                unsigned m = __ballot_sync(0xffffffffu, u < q);
                E = Enew;
                g_B[((size_t)i * BE + b) * KK + lane] = E;
                if (lane == 0) g_mask[(size_t)b * NN + i] = m;
            }
        }
    } else {
        // ------- fscan phase A: local chunk ESP, warp per (b, c) -------
        int wid = (blockIdx.x - 64) * 4 + (threadIdx.x >> 5);   // 0..8191
        int b = wid >> 5;
        int c = wid & 31;
        const int bz = b >> 1, e = b & 1;
        const float* thbase = scores + (size_t)bz * (NN * ENS) + e;

        float F = (lane == 0) ? 0.0f : NEGC;   // lane j holds log e_j
        int base0 = c * CLEN;
        for (int blk = 0; blk < CLEN / 32; ++blk) {
            float thv = thbase[2 * (base0 + blk * 32 + lane)];
#pragma unroll 8
            for (int ii = 0; ii < 32; ++ii) {
                float th = __shfl_sync(0xffffffffu, thv, ii);
                float Fp = __shfl_up_sync(0xffffffffu, F, 1);
                if (lane == 0) Fp = NEGC;
                F = logaddexp_fast(F, Fp + th);
            }
        }
        g_CE[((size_t)b * NCHUNK + c) * KK + lane] = F;
    }
}

// L2: chunk-boundary merge. Warp per b. P_{c+1}[j] = LSE_m(P_c[m] + L_c[j-m]).
__global__ void k_merge()
{
    int lane = threadIdx.x & 31;
    int b = blockIdx.x * 4 + (threadIdx.x >> 5);

    float P = (lane == 0) ? 0.0f : NEGC;
    for (int c = 0; c < NCHUNK; ++c) {
        g_BD[((size_t)b * NCHUNK + c) * KK + lane] = P;  // exclusive prefix
        float L = g_CE[((size_t)b * NCHUNK + c) * KK + lane];
        float mx = NEGC;
#pragma unroll
        for (int m = 0; m < 32; ++m) {
            float Pm = __shfl_sync(0xffffffffu, P, m);
            float Lx = __shfl_sync(0xffffffffu, L, (lane - m) & 31);
            if (m <= lane) mx = fmaxf(mx, Pm + Lx);
        }
        float s = 0.0f;
#pragma unroll
        for (int m = 0; m < 32; ++m) {
            float Pm = __shfl_sync(0xffffffffu, P, m);
            float Lx = __shfl_sync(0xffffffffu, L, (lane - m) & 31);
            if (m <= lane) s += __expf(Pm + Lx - mx);
        }
        P = mx + __logf(s);
    }
    if (lane == 31) g_logZ[b] = g_B[(size_t)b * KK + 31];   // B[0][b][32]
}

// sample helpers (unchanged numerics from passing R2 kernel)
__device__ __forceinline__ void samp_word(unsigned m, int ii, unsigned& r, unsigned& w)
{
    unsigned incl = (unsigned)(r > 0) & ((m >> ((r - 1u) & 31u)) & 1u);
    r -= incl;
    w |= incl << ii;
}

__device__ __forceinline__ unsigned samp_block(const uint4* buf, unsigned& r)
{
    unsigned w = 0;
#pragma unroll
    for (int q = 0; q < 8; ++q) {
        uint4 v = buf[q];
        samp_word(v.x, 4 * q + 0, r, w);
        samp_word(v.y, 4 * q + 1, r, w);
        samp_word(v.z, 4 * q + 2, r, w);
        samp_word(v.w, 4 * q + 3, r, w);
    }
    return w;
}

// L3: fused phase C (rescan chunk + inline comb -> marginals) + sampler blocks.
__global__ void k_phaseC(const float* __restrict__ scores)
{
    int lane = threadIdx.x & 31;

    if (blockIdx.x < 2048) {
        // ------- phase C: warp per (b, c) -------
        int wid = blockIdx.x * 4 + (threadIdx.x >> 5);
        int b = wid >> 5;
        int c = wid & 31;
        const int bz = b >> 1, e = b & 1;
        const float* thbase = scores + (size_t)bz * (NN * ENS) + e;

        float F = g_BD[((size_t)b * NCHUNK + c) * KK + lane];
        float logZ = g_logZ[b];
        int base0 = c * CLEN;

        for (int blk = 0; blk < CLEN / 32; ++blk) {
            float thv = thbase[2 * (base0 + blk * 32 + lane)];
            float mreg = 0.0f;
#pragma unroll 4
            for (int ii = 0; ii < 32; ++ii) {
                int i = base0 + blk * 32 + ii;
                // B[i+1] row: offset lane holds column lane+1
                float Bv = g_B[((size_t)(i + 1) * BE + b) * KK + lane];
                float th = __shfl_sync(0xffffffffu, thv, ii);
                // lane j needs B[i+1][31-j]: column 31-j at offset 30-j; col 0 == 0
                float Brev = __shfl_sync(0xffffffffu, Bv, (30 - lane) & 31);
                if (lane == 31) Brev = 0.0f;
                // marginal term: exp(F[i][j] + B[i+1][31-j] + th - logZ) in [0,1]
                float t = __expf(F + Brev + th - logZ);
#pragma unroll
                for (int s = 16; s; s >>= 1) t += __shfl_xor_sync(0xffffffffu, t, s);
                if (lane == ii) mreg = t;
                // chain update (pre-update F was used above)
                float Fp = __shfl_up_sync(0xffffffffu, F, 1);
                if (lane == 0) Fp = NEGC;
                F = logaddexp_fast(F, Fp + th);
            }
            g_M[(size_t)b * NN + base0 + blk * 32 + lane] = mreg;
        }
    } else {
        // ------- sampler: thread per b -------
        int b = (blockIdx.x - 2048) * 128 + threadIdx.x;
        if (b >= BE) return;
        const uint4* mp = reinterpret_cast<const uint4*>(g_mask + (size_t)b * NN);
        unsigned r = KK;
        uint4 A[8], Bb[8];
#pragma unroll
        for (int q = 0; q < 8; ++q) A[q] = mp[q];
        for (int blk = 0; blk < 128; blk += 2) {
#pragma unroll
            for (int q = 0; q < 8; ++q) Bb[q] = mp[(blk + 1) * 8 + q];
            g_bits[(size_t)b * 128 + blk] = samp_block(A, r);
            if (blk + 2 < 128) {
#pragma unroll
                for (int q = 0; q < 8; ++q) A[q] = mp[(blk + 2) * 8 + q];
            }
            g_bits[(size_t)b * 128 + blk + 1] = samp_block(Bb, r);
        }
    }
}

// L4: finalize outputs (pure repack).
__global__ void k_final(float* __restrict__ out)
{
    int tid = blockIdx.x * blockDim.x + threadIdx.x;  // 0 .. 2^20-1
    int bz = tid >> 13;
    int rem = tid & 8191;
    int n = rem >> 1;
    int e = rem & 1;
    int be = bz * ENS + e;
    float s = (float)((g_bits[(size_t)be * (NN / 32) + (n >> 5)] >> (n & 31)) & 1u);
    float m = g_M[(size_t)be * NN + n];
    out[tid] = (s - m) + m;
    out[HALF_OUT + tid] = m;
}

extern "C" void kernel_launch(void* const* d_in, const int* in_sizes, int n_in,
                              void* d_out, int out_size)
{
    const float* scores = (const float*)d_in[0];
    float* out = (float*)d_out;
    (void)in_sizes; (void)n_in; (void)out_size;

    k_rand<<<1024, 1024>>>();
    k_scanAB<<<2112, 128>>>(scores);
    k_merge<<<64, 128>>>();
    k_phaseC<<<2050, 128>>>(scores);
    k_final<<<1024, 1024>>>(out);
}

// round 4
// speedup vs baseline: 3.8677x; 1.0602x over previous
#include <cuda_runtime.h>
#include <stdint.h>
#include <math.h>

// Problem constants (fixed shapes from reference: scores (128, 4096, 2))
#define NN   4096
#define BSZ  128
#define ENS  2
#define BE   256           // BSZ*ENS
#define KK   32
#define NEGC (-1e30f)
#define HALF_OUT 1048576   // 128*4096*2
#define NCHUNK 32
#define CLEN   128         // NN / NCHUNK
#define NSLICE 8
#define SLEN   512         // NN / NSLICE

// ---------------- scratch (static device memory; no allocations) ----------------
__device__ float    g_B[(size_t)(NN + 1) * BE * KK]; // B[i][b][j-1], j=1..32
__device__ float    g_F[(size_t)NN * BE * KK];       // F[i][b][j], j=0..31 (pre-update)
__device__ float    g_U[(size_t)BE * NN];            // uniforms [b*NN + i]
__device__ unsigned g_mask[(size_t)BE * NN];         // inclusion masks [b*NN + i]
__device__ float    g_CE[(size_t)BE * NCHUNK * KK];  // chunk ESPs
__device__ float    g_BD[(size_t)BE * NCHUNK * KK];  // chunk boundary prefixes
__device__ float    g_S[(size_t)NN * BE];            // th + log_ekm1 (unnormalized)
__device__ float    g_T[(size_t)NN * BE];            // transposed theta [i*BE + b]
__device__ float    g_E[(size_t)BE * KK];            // backward scan state between slices
__device__ float    g_logZ[BE];
__device__ unsigned g_bits[(size_t)BE * (NN / 32)];  // sampled bits

// ---------------- threefry2x32, key = (0, 42) ----------------
__device__ __forceinline__ uint32_t tf_bits(uint32_t lo)
{
    uint32_t x0 = 0u;
    uint32_t x1 = lo;
    const uint32_t ks0 = 0u, ks1 = 42u, ks2 = 0x1BD11BF0u;
    x0 += ks0; x1 += ks1;
#define TFR(r) { x0 += x1; x1 = (x1 << (r)) | (x1 >> (32 - (r))); x1 ^= x0; }
    TFR(13) TFR(15) TFR(26) TFR(6)   x0 += ks1; x1 += ks2 + 1u;
    TFR(17) TFR(29) TFR(16) TFR(24)  x0 += ks2; x1 += ks0 + 2u;
    TFR(13) TFR(15) TFR(26) TFR(6)   x0 += ks0; x1 += ks1 + 3u;
    TFR(17) TFR(29) TFR(16) TFR(24)  x0 += ks1; x1 += ks2 + 4u;
    TFR(13) TFR(15) TFR(26) TFR(6)   x0 += ks2; x1 += ks0 + 5u;
#undef TFR
    return x0 ^ x1;
}

__global__ void k_rand()
{
    int tid = blockIdx.x * blockDim.x + threadIdx.x;
    int b = tid >> 12;
    int i = tid & (NN - 1);
    uint32_t bits = tf_bits((uint32_t)(i * BE + b));
    float f = __uint_as_float((bits >> 9) | 0x3f800000u) - 1.0f;
    g_U[(size_t)b * NN + i] = fmaxf(f, 0.0f);
}

// EXACT logaddexp (libdevice — bitwise path for sampling masks)
__device__ __forceinline__ float logaddexpf32(float x, float y)
{
    float d = x - y;
    return fmaxf(x, y) + log1pf(expf(-fabsf(d)));
}

// Fast logaddexp (marginals path, 1e-3 tolerance)
__device__ __forceinline__ float logaddexp_fast(float x, float y)
{
    float d = x - y;
    return fmaxf(x, y) + __logf(1.0f + __expf(-fabsf(d)));
}

// -------------------- work pieces (device functions) --------------------

// Backward scan slice: 512 exact steps, state checkpointed in g_E.
__device__ void backward_slice(const float* __restrict__ scores, int s)
{
    int lane = threadIdx.x & 31;
    int b = blockIdx.x * 4 + (threadIdx.x >> 5);
    const int bz = b >> 1, e = b & 1;
    const float* thbase = scores + (size_t)bz * (NN * ENS) + e;

    float E;
    if (s == 0) {
        E = NEGC;
        g_B[((size_t)NN * BE + b) * KK + lane] = NEGC;   // init row (i = NN)
    } else {
        E = g_E[(size_t)b * KK + lane];
    }

    int blk_hi = (NN / 32) - 16 * s;        // exclusive
    int blk_lo = (NN / 32) - 16 * (s + 1);
    for (int blk = blk_hi - 1; blk >= blk_lo; --blk) {
        int base = blk * 32;
        float thv = thbase[2 * (base + lane)];
        float uv  = g_U[(size_t)b * NN + base + lane];
#pragma unroll 8
        for (int ii = 31; ii >= 0; --ii) {
            int i = base + ii;
            float th = __shfl_sync(0xffffffffu, thv, ii);
            float u  = __shfl_sync(0xffffffffu, uv,  ii);
            float Ep = __shfl_up_sync(0xffffffffu, E, 1);
            if (lane == 0) Ep = 0.0f;
            float shifted = Ep + th;
            float Enew = logaddexpf32(E, shifted);
            float logq = shifted - Enew;
            float q = expf(fminf(logq, 0.0f));
            unsigned m = __ballot_sync(0xffffffffu, u < q);
            E = Enew;
            g_B[((size_t)i * BE + b) * KK + lane] = E;
            if (lane == 0) g_mask[(size_t)b * NN + i] = m;
        }
    }
    g_E[(size_t)b * KK + lane] = E;
}

// Phase A: per-chunk local ESPs (fast math).
__device__ void phaseA(const float* __restrict__ scores, int xb)
{
    int lane = threadIdx.x & 31;
    int wid = xb * 4 + (threadIdx.x >> 5);   // 0..8191
    int b = wid >> 5;
    int c = wid & 31;
    const int bz = b >> 1, e = b & 1;
    const float* thbase = scores + (size_t)bz * (NN * ENS) + e;

    float F = (lane == 0) ? 0.0f : NEGC;
    int base0 = c * CLEN;
    for (int blk = 0; blk < CLEN / 32; ++blk) {
        float thv = thbase[2 * (base0 + blk * 32 + lane)];
#pragma unroll 8
        for (int ii = 0; ii < 32; ++ii) {
            float th = __shfl_sync(0xffffffffu, thv, ii);
            float Fp = __shfl_up_sync(0xffffffffu, F, 1);
            if (lane == 0) Fp = NEGC;
            F = logaddexp_fast(F, Fp + th);
        }
    }
    g_CE[((size_t)b * NCHUNK + c) * KK + lane] = F;
}

// Theta transpose into [i*BE + b] (coalesced writes for comb).
__device__ void transpose_theta(const float* __restrict__ scores, int xb)
{
    int idx = (xb * 128 + threadIdx.x) * 4;
#pragma unroll
    for (int q = 0; q < 4; ++q, ++idx) {
        int b = idx & (BE - 1);
        int i = idx >> 8;
        g_T[idx] = scores[(size_t)(b >> 1) * (NN * ENS) + i * ENS + (b & 1)];
    }
}

// Merge: chunk boundary prefixes via log-domain ESP convolution.
__device__ void merge_chunks(int xb)
{
    int lane = threadIdx.x & 31;
    int b = xb * 4 + (threadIdx.x >> 5);

    float P = (lane == 0) ? 0.0f : NEGC;
    for (int c = 0; c < NCHUNK; ++c) {
        g_BD[((size_t)b * NCHUNK + c) * KK + lane] = P;  // exclusive prefix
        float L = g_CE[((size_t)b * NCHUNK + c) * KK + lane];
        float mx = NEGC;
#pragma unroll
        for (int m = 0; m < 32; ++m) {
            float Pm = __shfl_sync(0xffffffffu, P, m);
            float Lx = __shfl_sync(0xffffffffu, L, (lane - m) & 31);
            if (m <= lane) mx = fmaxf(mx, Pm + Lx);
        }
        float sum = 0.0f;
#pragma unroll
        for (int m = 0; m < 32; ++m) {
            float Pm = __shfl_sync(0xffffffffu, P, m);
            float Lx = __shfl_sync(0xffffffffu, L, (lane - m) & 31);
            if (m <= lane) sum += __expf(Pm + Lx - mx);
        }
        P = mx + __logf(sum);
    }
}

// Phase C: rescan each chunk from boundary state, storing pre-update F rows.
__device__ void phaseC_storeF(const float* __restrict__ scores, int xb)
{
    int lane = threadIdx.x & 31;
    int wid = xb * 4 + (threadIdx.x >> 5);
    int b = wid >> 5;
    int c = wid & 31;
    const int bz = b >> 1, e = b & 1;
    const float* thbase = scores + (size_t)bz * (NN * ENS) + e;

    float F = g_BD[((size_t)b * NCHUNK + c) * KK + lane];
    int base0 = c * CLEN;
    for (int blk = 0; blk < CLEN / 32; ++blk) {
        float thv = thbase[2 * (base0 + blk * 32 + lane)];
#pragma unroll 8
        for (int ii = 0; ii < 32; ++ii) {
            int i = base0 + blk * 32 + ii;
            g_F[((size_t)i * BE + b) * KK + lane] = F;
            float th = __shfl_sync(0xffffffffu, thv, ii);
            float Fp = __shfl_up_sync(0xffffffffu, F, 1);
            if (lane == 0) Fp = NEGC;
            F = logaddexp_fast(F, Fp + th);
        }
    }
}

// Comb: one thread per (i,b) in [rowbase, rowbase+nrows). Streams F and B rows,
// computes s_i = th_i + logsumexp_j(F[i][j] + B[i+1][31-j]).
__device__ void comb_band(int xb, int rowbase)
{
    int tid = xb * 128 + threadIdx.x;
    int b = tid & (BE - 1);
    int i = rowbase + (tid >> 8);

    const float4* Fr = reinterpret_cast<const float4*>(&g_F[((size_t)i * BE + b) * KK]);
    const float4* Br = reinterpret_cast<const float4*>(&g_B[((size_t)(i + 1) * BE + b) * KK]);

    float Fv[32], Bv[32];
#pragma unroll
    for (int q = 0; q < 8; ++q) {
        float4 f4 = Fr[q];
        Fv[4 * q + 0] = f4.x; Fv[4 * q + 1] = f4.y; Fv[4 * q + 2] = f4.z; Fv[4 * q + 3] = f4.w;
        float4 b4 = Br[q];
        Bv[4 * q + 0] = b4.x; Bv[4 * q + 1] = b4.y; Bv[4 * q + 2] = b4.z; Bv[4 * q + 3] = b4.w;
    }

    float comb[32];
#pragma unroll
    for (int j = 0; j < 32; ++j) {
        float bc = (j == 31) ? 0.0f : Bv[30 - j];   // B[i+1][31-j]; col 0 == 0
        comb[j] = Fv[j] + bc;
    }
    float mx = comb[0];
#pragma unroll
    for (int j = 1; j < 32; ++j) mx = fmaxf(mx, comb[j]);
    float sum = 0.0f;
#pragma unroll
    for (int j = 0; j < 32; ++j) sum += __expf(comb[j] - mx);

    g_S[(size_t)i * BE + b] = g_T[(size_t)i * BE + b] + mx + __logf(sum);
}

// -------------------- sliced fused kernel --------------------

__global__ void k_slice(const float* __restrict__ scores, int s)
{
    if (blockIdx.x < 64) {
        backward_slice(scores, s);
        return;
    }
    int xb = blockIdx.x - 64;
    if (s == 0) {
        if (xb < 2048) phaseA(scores, xb);
        else transpose_theta(scores, xb - 2048);
    } else if (s == 1) {
        merge_chunks(xb);
    } else if (s == 2) {
        phaseC_storeF(scores, xb);
    } else {
        // comb bands chase the backward scan down:
        // s=3 -> rows [2560,4096); s=4..7 -> [4096-512s, 4096-512(s-1))
        int rowbase = (s == 3) ? 2560 : (NN - SLEN * s);
        comb_band(xb, rowbase);
    }
}

// -------------------- tail: last comb band + sampler --------------------

__device__ __forceinline__ void samp_word(unsigned m, int ii, unsigned& r, unsigned& w)
{
    unsigned incl = (unsigned)(r > 0) & ((m >> ((r - 1u) & 31u)) & 1u);
    r -= incl;
    w |= incl << ii;
}

__device__ __forceinline__ unsigned samp_block(const uint4* buf, unsigned& r)
{
    unsigned w = 0;
#pragma unroll
    for (int q = 0; q < 8; ++q) {
        uint4 v = buf[q];
        samp_word(v.x, 4 * q + 0, r, w);
        samp_word(v.y, 4 * q + 1, r, w);
        samp_word(v.z, 4 * q + 2, r, w);
        samp_word(v.w, 4 * q + 3, r, w);
    }
    return w;
}

__global__ void k_tail()
{
    if (blockIdx.x < 1024) {
        comb_band(blockIdx.x, 0);           // rows [0, 512)
        return;
    }
    // sampler: thread per b
    int b = (blockIdx.x - 1024) * 128 + threadIdx.x;
    if (b >= BE) return;
    g_logZ[b] = g_B[(size_t)b * KK + 31];   // B[0][b][32] = logZ

    const uint4* mp = reinterpret_cast<const uint4*>(g_mask + (size_t)b * NN);
    unsigned r = KK;
    uint4 A[8], Bb[8];
#pragma unroll
    for (int q = 0; q < 8; ++q) A[q] = mp[q];
    for (int blk = 0; blk < 128; blk += 2) {
#pragma unroll
        for (int q = 0; q < 8; ++q) Bb[q] = mp[(blk + 1) * 8 + q];
        g_bits[(size_t)b * 128 + blk] = samp_block(A, r);
        if (blk + 2 < 128) {
#pragma unroll
            for (int q = 0; q < 8; ++q) A[q] = mp[(blk + 2) * 8 + q];
        }
        g_bits[(size_t)b * 128 + blk + 1] = samp_block(Bb, r);
    }
}

// -------------------- finalize --------------------

__global__ void k_final(float* __restrict__ out)
{
    int tid = blockIdx.x * blockDim.x + threadIdx.x;  // 0 .. 2^20-1
    int bz = tid >> 13;
    int rem = tid & 8191;
    int n = rem >> 1;
    int e = rem & 1;
    int be = bz * ENS + e;
    float s = (float)((g_bits[(size_t)be * (NN / 32) + (n >> 5)] >> (n & 31)) & 1u);
    float m = __expf(g_S[(size_t)n * BE + be] - g_logZ[be]);
    out[tid] = (s - m) + m;
    out[HALF_OUT + tid] = m;
}

extern "C" void kernel_launch(void* const* d_in, const int* in_sizes, int n_in,
                              void* d_out, int out_size)
{
    const float* scores = (const float*)d_in[0];
    float* out = (float*)d_out;
    (void)in_sizes; (void)n_in; (void)out_size;

    k_rand<<<1024, 1024>>>();
    k_slice<<<64 + 2048 + 2048, 128>>>(scores, 0);  // backward + phaseA + transpose
    k_slice<<<64 + 64,          128>>>(scores, 1);  // backward + merge
    k_slice<<<64 + 2048,        128>>>(scores, 2);  // backward + phaseC (store F)
    k_slice<<<64 + 3072,        128>>>(scores, 3);  // backward + comb [2560,4096)
    k_slice<<<64 + 1024,        128>>>(scores, 4);  // backward + comb [2048,2560)
    k_slice<<<64 + 1024,        128>>>(scores, 5);  // backward + comb [1536,2048)
    k_slice<<<64 + 1024,        128>>>(scores, 6);  // backward + comb [1024,1536)
    k_slice<<<64 + 1024,        128>>>(scores, 7);  // backward + comb [512,1024)
    k_tail<<<1026, 128>>>();                        // comb [0,512) + sampler
    k_final<<<2048, 512>>>(out);
}